// round 9
// baseline (speedup 1.0000x reference)
#include <cuda_runtime.h>
#include <cuda_bf16.h>
#include <cstdint>

// Problem constants (fixed shapes for this problem instance).
#define NN 50000
#define DD 256
#define EE 400000

// ---------------- device scratch (no allocations allowed) ----------------
__device__ float g_h[NN * DD];        // h = feat @ Wsum  (51.2 MB, mostly L2-resident)
__device__ float g_W[DD * DD];        // (W0+W1+W2)/3
__device__ int   g_deg[3][NN];
__device__ int   g_off[3][NN];
__device__ int   g_cur[3][NN];
__device__ int   g_csr[3][EE];

// ---------------- f32x2 packed helpers (sm_103a FFMA2 path) ----------------
__device__ __forceinline__ unsigned long long pack2(float x, float y) {
    unsigned long long r;
    asm("mov.b64 %0, {%1, %2};" : "=l"(r) : "f"(x), "f"(y));
    return r;
}
__device__ __forceinline__ void ffma2(unsigned long long& d,
                                      unsigned long long a,
                                      unsigned long long b) {
    asm("fma.rn.f32x2 %0, %1, %2, %0;" : "+l"(d) : "l"(a), "l"(b));
}
__device__ __forceinline__ float2 unpack2(unsigned long long v) {
    float2 f;
    asm("mov.b64 {%0, %1}, %2;" : "=f"(f.x), "=f"(f.y) : "l"(v));
    return f;
}

// ---------------- tiny kernels ----------------
__global__ void zero_kernel() {
    int i = blockIdx.x * blockDim.x + threadIdx.x;
    if (i < 3 * NN) {
        (&g_deg[0][0])[i] = 0;
        (&g_cur[0][0])[i] = 0;
    }
}

__global__ void wsum_kernel(const float* __restrict__ W0,
                            const float* __restrict__ W1,
                            const float* __restrict__ W2) {
    int i = blockIdx.x * blockDim.x + threadIdx.x;
    if (i < DD * DD)
        g_W[i] = (W0[i] + W1[i] + W2[i]) * (1.0f / 3.0f);
}

__global__ void deg_kernel(const int* __restrict__ d0,
                           const int* __restrict__ d1,
                           const int* __restrict__ d2, int E) {
    int i = blockIdx.x * blockDim.x + threadIdx.x;
    if (i >= 3 * E) return;
    int r = i / E;
    int e = i - r * E;
    const int* dp = (r == 0) ? d0 : (r == 1) ? d1 : d2;
    atomicAdd(&g_deg[r][dp[e]], 1);
}

// One block per relation: coalesced tiled scan (warp shuffles + carry).
__global__ __launch_bounds__(1024)
void scan_kernel(int n) {
    int r = blockIdx.x;           // 0..2
    int tid = threadIdx.x;        // 0..1023
    int lane = tid & 31, wid = tid >> 5;
    const int* deg = g_deg[r];
    int* off = g_off[r];

    __shared__ int warpsum[32];
    __shared__ int s_carry;
    if (tid == 0) s_carry = 0;
    __syncthreads();

    for (int base = 0; base < n; base += 1024) {
        int idx = base + tid;
        int v = (idx < n) ? deg[idx] : 0;
        // inclusive warp scan
        int x = v;
#pragma unroll
        for (int o = 1; o < 32; o <<= 1) {
            int t = __shfl_up_sync(0xFFFFFFFFu, x, o);
            if (lane >= o) x += t;
        }
        if (lane == 31) warpsum[wid] = x;
        __syncthreads();
        if (wid == 0) {
            int w = warpsum[lane];
#pragma unroll
            for (int o = 1; o < 32; o <<= 1) {
                int t = __shfl_up_sync(0xFFFFFFFFu, w, o);
                if (lane >= o) w += t;
            }
            warpsum[lane] = w;
        }
        __syncthreads();
        int carry = s_carry;
        int excl = carry + (wid ? warpsum[wid - 1] : 0) + x - v;
        if (idx < n) off[idx] = excl;
        __syncthreads();                 // everyone read s_carry & warpsum
        if (tid == 0) s_carry = carry + warpsum[31];
        __syncthreads();
    }
}

__global__ void fill_kernel(const int* __restrict__ s0, const int* __restrict__ d0,
                            const int* __restrict__ s1, const int* __restrict__ d1,
                            const int* __restrict__ s2, const int* __restrict__ d2,
                            int E) {
    int i = blockIdx.x * blockDim.x + threadIdx.x;
    if (i >= 3 * E) return;
    int r = i / E;
    int e = i - r * E;
    const int* sp = (r == 0) ? s0 : (r == 1) ? s1 : s2;
    const int* dp = (r == 0) ? d0 : (r == 1) ? d1 : d2;
    int dst = dp[e];
    int pos = g_off[r][dst] + atomicAdd(&g_cur[r][dst], 1);
    g_csr[r][pos] = sp[e];
}

// ---------------- SGEMM: g_h[M,256] = A[M,256] @ g_W[256,256] ----------------
// 128x128 block tile, BK=16, 256 threads, 8x8 per-thread microtile,
// inner product via packed fma.rn.f32x2 (2 fp32 FMA per fma-pipe slot).
__global__ __launch_bounds__(256, 2)
void gemm_kernel(const float* __restrict__ A, int M) {
    const int K = DD;
    __shared__ float As[16][128];   // transposed A tile: As[k][m]
    __shared__ float Bs[16][128];   // Bs[k][n]

    int tid = threadIdx.x;
    int tx = tid & 15;              // 0..15 (n groups)
    int ty = tid >> 4;              // 0..15 (m groups)
    int rowBase = blockIdx.x * 128;
    int colBase = blockIdx.y * 128;

    // acc2[i][j] packs columns (tx*8+2j, tx*8+2j+1) for row ty*8+i
    unsigned long long acc2[8][4];
#pragma unroll
    for (int i = 0; i < 8; i++)
#pragma unroll
        for (int j = 0; j < 4; j++) acc2[i][j] = 0ULL;

    for (int k0 = 0; k0 < K; k0 += 16) {
        // Load A tile (128x16): 512 float4s, 2 per thread.
#pragma unroll
        for (int l = 0; l < 2; l++) {
            int f = tid + l * 256;      // 0..511
            int ar = f >> 2;            // 0..127 (m)
            int ac = (f & 3) * 4;       // 0,4,8,12 (k)
            float4 v = make_float4(0.f, 0.f, 0.f, 0.f);
            int grow = rowBase + ar;
            if (grow < M)
                v = *(const float4*)&A[(size_t)grow * K + k0 + ac];
            As[ac + 0][ar] = v.x;
            As[ac + 1][ar] = v.y;
            As[ac + 2][ar] = v.z;
            As[ac + 3][ar] = v.w;
        }
        // Load B tile (16x128): 512 float4s, 2 per thread.
#pragma unroll
        for (int l = 0; l < 2; l++) {
            int f = tid + l * 256;
            int br = f >> 5;            // 0..15 (k)
            int bc = (f & 31) * 4;      // 0..124 (n)
            float4 v = *(const float4*)&g_W[(size_t)(k0 + br) * DD + colBase + bc];
            *(float4*)&Bs[br][bc] = v;
        }
        __syncthreads();
#pragma unroll
        for (int kk = 0; kk < 16; kk++) {
            // B column-pairs: contiguous 64-bit loads from shared (32B aligned)
            const unsigned long long* bp =
                (const unsigned long long*)&Bs[kk][tx * 8];
            unsigned long long b2[4];
            b2[0] = bp[0]; b2[1] = bp[1]; b2[2] = bp[2]; b2[3] = bp[3];

            float4 a0v = *(const float4*)&As[kk][ty * 8];
            float4 a1v = *(const float4*)&As[kk][ty * 8 + 4];
            unsigned long long a2[8];
            a2[0] = pack2(a0v.x, a0v.x);
            a2[1] = pack2(a0v.y, a0v.y);
            a2[2] = pack2(a0v.z, a0v.z);
            a2[3] = pack2(a0v.w, a0v.w);
            a2[4] = pack2(a1v.x, a1v.x);
            a2[5] = pack2(a1v.y, a1v.y);
            a2[6] = pack2(a1v.z, a1v.z);
            a2[7] = pack2(a1v.w, a1v.w);
#pragma unroll
            for (int i = 0; i < 8; i++)
#pragma unroll
                for (int j = 0; j < 4; j++)
                    ffma2(acc2[i][j], a2[i], b2[j]);
        }
        __syncthreads();
    }
    // Store
#pragma unroll
    for (int i = 0; i < 8; i++) {
        int grow = rowBase + ty * 8 + i;
        if (grow < M) {
            float2 p0 = unpack2(acc2[i][0]);
            float2 p1 = unpack2(acc2[i][1]);
            float2 p2 = unpack2(acc2[i][2]);
            float2 p3 = unpack2(acc2[i][3]);
            float4 v0 = make_float4(p0.x, p0.y, p1.x, p1.y);
            float4 v1 = make_float4(p2.x, p2.y, p3.x, p3.y);
            float* dst = &g_h[(size_t)grow * DD + colBase + tx * 8];
            *(float4*)dst = v0;
            *(float4*)(dst + 4) = v1;
        }
    }
}

// ---------------- gather + cross-relation mean + relu + LayerNorm ----------------
// One block (256 threads) per destination node; thread t owns feature dim t.
__global__ __launch_bounds__(256)
void agg_ln_kernel(const float* __restrict__ gamma,
                   const float* __restrict__ beta,
                   float* __restrict__ out, int n) {
    int v = blockIdx.x;
    if (v >= n) return;
    int tid = threadIdx.x;

    __shared__ int es[128];
    float acc = 0.f;

#pragma unroll
    for (int r = 0; r < 3; r++) {
        int dg = g_deg[r][v];          // uniform across block
        if (dg == 0) continue;
        int o = g_off[r][v];
        float accR = 0.f;
        for (int base = 0; base < dg; base += 128) {
            int cnt = min(128, dg - base);
            if (tid < cnt) es[tid] = g_csr[r][o + base + tid];
            __syncthreads();
#pragma unroll 4
            for (int i = 0; i < cnt; i++) {
                const float* hp = g_h + (size_t)es[i] * DD;
                accR += hp[tid];
            }
            __syncthreads();
        }
        acc += accR * (1.0f / (3.0f * (float)dg));
    }

    float x = fmaxf(acc, 0.f);

    // block reduce sum & sumsq over 256 lanes
    float s1 = x, s2 = x * x;
#pragma unroll
    for (int o = 16; o > 0; o >>= 1) {
        s1 += __shfl_xor_sync(0xFFFFFFFFu, s1, o);
        s2 += __shfl_xor_sync(0xFFFFFFFFu, s2, o);
    }
    __shared__ float w1[8], w2[8];
    int wid = tid >> 5, lane = tid & 31;
    if (lane == 0) { w1[wid] = s1; w2[wid] = s2; }
    __syncthreads();
    s1 = 0.f; s2 = 0.f;
#pragma unroll
    for (int i = 0; i < 8; i++) { s1 += w1[i]; s2 += w2[i]; }

    float mean = s1 * (1.0f / 256.0f);
    float var = s2 * (1.0f / 256.0f) - mean * mean;
    var = fmaxf(var, 0.f);
    float inv = rsqrtf(var + 1e-5f);
    out[(size_t)v * DD + tid] = (x - mean) * inv * gamma[tid] + beta[tid];
}

// ---------------- launch ----------------
extern "C" void kernel_launch(void* const* d_in, const int* in_sizes, int n_in,
                              void* d_out, int out_size) {
    const float* feat  = (const float*)d_in[0];
    const float* W0    = (const float*)d_in[1];
    const float* W1    = (const float*)d_in[2];
    const float* W2    = (const float*)d_in[3];
    // d_in[4..6] = a0,a1,a2 : softmax over size-1 tensors -> exactly 1/3 weights; unused.
    const float* gamma = (const float*)d_in[7];
    const float* beta  = (const float*)d_in[8];
    const int* src0 = (const int*)d_in[9];
    const int* dst0 = (const int*)d_in[10];
    const int* src1 = (const int*)d_in[11];
    const int* dst1 = (const int*)d_in[12];
    const int* src2 = (const int*)d_in[13];
    const int* dst2 = (const int*)d_in[14];

    int N = in_sizes[0] / DD;     // 50000
    int E = in_sizes[9];          // 400000

    // Lazily-created side stream + fork/join events (handles only; no device
    // memory). Work issued per call is identical every call.
    static cudaStream_t s_side = nullptr;
    static cudaEvent_t  ev_fork = nullptr, ev_join = nullptr;
    if (s_side == nullptr) {
        cudaStreamCreateWithFlags(&s_side, cudaStreamNonBlocking);
        cudaEventCreateWithFlags(&ev_fork, cudaEventDisableTiming);
        cudaEventCreateWithFlags(&ev_join, cudaEventDisableTiming);
    }

    // Fork: CSR-build chain runs on s_side, concurrent with the GEMM chain.
    cudaEventRecord(ev_fork, 0);
    cudaStreamWaitEvent(s_side, ev_fork, 0);

    // Branch B (side stream): CSR build
    zero_kernel<<<(3 * NN + 255) / 256, 256, 0, s_side>>>();
    deg_kernel<<<(3 * E + 255) / 256, 256, 0, s_side>>>(dst0, dst1, dst2, E);
    scan_kernel<<<3, 1024, 0, s_side>>>(N);
    fill_kernel<<<(3 * E + 255) / 256, 256, 0, s_side>>>(src0, dst0, src1, dst1,
                                                         src2, dst2, E);
    cudaEventRecord(ev_join, s_side);

    // Branch A (main stream): weight sum + GEMM
    wsum_kernel<<<(DD * DD + 255) / 256, 256>>>(W0, W1, W2);
    dim3 ggrid((N + 127) / 128, DD / 128);
    gemm_kernel<<<ggrid, 256>>>(feat, N);

    // Join: agg needs both g_h (branch A) and the CSR (branch B).
    cudaStreamWaitEvent(0, ev_join, 0);
    agg_ln_kernel<<<N, 256>>>(gamma, beta, (float*)d_out, N);
}

// round 10
// speedup vs baseline: 1.4546x; 1.4546x over previous
#include <cuda_runtime.h>
#include <cuda_bf16.h>
#include <cstdint>

// Problem constants (fixed shapes for this problem instance).
#define NN 50000
#define DD 256
#define EE 400000

// ---------------- device scratch (no allocations allowed) ----------------
__device__ float g_h[NN * DD];        // h = feat @ Wsum  (51.2 MB, mostly L2-resident)
__device__ float g_W[DD * DD];        // (W0+W1+W2)/3
__device__ int   g_deg[3][NN];
__device__ int   g_off[3][NN];
__device__ int   g_cur[3][NN];
__device__ int   g_csr[3][EE];

// ---------------- tiny kernels ----------------
__global__ void zero_kernel() {
    int i = blockIdx.x * blockDim.x + threadIdx.x;
    if (i < 3 * NN) {
        (&g_deg[0][0])[i] = 0;
        (&g_cur[0][0])[i] = 0;
    }
}

__global__ void wsum_kernel(const float* __restrict__ W0,
                            const float* __restrict__ W1,
                            const float* __restrict__ W2) {
    int i = blockIdx.x * blockDim.x + threadIdx.x;
    if (i < DD * DD)
        g_W[i] = (W0[i] + W1[i] + W2[i]) * (1.0f / 3.0f);
}

__global__ void deg_kernel(const int* __restrict__ d0,
                           const int* __restrict__ d1,
                           const int* __restrict__ d2, int E) {
    int i = blockIdx.x * blockDim.x + threadIdx.x;
    if (i >= 3 * E) return;
    int r = i / E;
    int e = i - r * E;
    const int* dp = (r == 0) ? d0 : (r == 1) ? d1 : d2;
    atomicAdd(&g_deg[r][dp[e]], 1);
}

// One block per relation: coalesced tiled scan (warp shuffles + carry).
__global__ __launch_bounds__(1024)
void scan_kernel(int n) {
    int r = blockIdx.x;           // 0..2
    int tid = threadIdx.x;        // 0..1023
    int lane = tid & 31, wid = tid >> 5;
    const int* deg = g_deg[r];
    int* off = g_off[r];

    __shared__ int warpsum[32];
    __shared__ int s_carry;
    if (tid == 0) s_carry = 0;
    __syncthreads();

    for (int base = 0; base < n; base += 1024) {
        int idx = base + tid;
        int v = (idx < n) ? deg[idx] : 0;
        // inclusive warp scan
        int x = v;
#pragma unroll
        for (int o = 1; o < 32; o <<= 1) {
            int t = __shfl_up_sync(0xFFFFFFFFu, x, o);
            if (lane >= o) x += t;
        }
        if (lane == 31) warpsum[wid] = x;
        __syncthreads();
        if (wid == 0) {
            int w = warpsum[lane];
#pragma unroll
            for (int o = 1; o < 32; o <<= 1) {
                int t = __shfl_up_sync(0xFFFFFFFFu, w, o);
                if (lane >= o) w += t;
            }
            warpsum[lane] = w;
        }
        __syncthreads();
        int carry = s_carry;
        int excl = carry + (wid ? warpsum[wid - 1] : 0) + x - v;
        if (idx < n) off[idx] = excl;
        __syncthreads();                 // everyone read s_carry & warpsum
        if (tid == 0) s_carry = carry + warpsum[31];
        __syncthreads();
    }
}

__global__ void fill_kernel(const int* __restrict__ s0, const int* __restrict__ d0,
                            const int* __restrict__ s1, const int* __restrict__ d1,
                            const int* __restrict__ s2, const int* __restrict__ d2,
                            int E) {
    int i = blockIdx.x * blockDim.x + threadIdx.x;
    if (i >= 3 * E) return;
    int r = i / E;
    int e = i - r * E;
    const int* sp = (r == 0) ? s0 : (r == 1) ? s1 : s2;
    const int* dp = (r == 0) ? d0 : (r == 1) ? d1 : d2;
    int dst = dp[e];
    int pos = g_off[r][dst] + atomicAdd(&g_cur[r][dst], 1);
    g_csr[r][pos] = sp[e];
}

// ---------------- SGEMM: g_h[M,256] = A[M,256] @ g_W[256,256] ----------------
// 128x128 block tile, BK=16, 256 threads, 8x8 per-thread microtile.
// (Plain-FFMA version — the f32x2 packed variant regressed from register-pair
//  pressure/spills under the 128-reg occupancy-2 cap.)
__global__ __launch_bounds__(256, 2)
void gemm_kernel(const float* __restrict__ A, int M) {
    const int K = DD;
    __shared__ float As[16][128];   // transposed A tile: As[k][m]
    __shared__ float Bs[16][128];   // Bs[k][n]

    int tid = threadIdx.x;
    int tx = tid & 15;              // 0..15 (n groups)
    int ty = tid >> 4;              // 0..15 (m groups)
    int rowBase = blockIdx.x * 128;
    int colBase = blockIdx.y * 128;

    float acc[8][8];
#pragma unroll
    for (int i = 0; i < 8; i++)
#pragma unroll
        for (int j = 0; j < 8; j++) acc[i][j] = 0.f;

    for (int k0 = 0; k0 < K; k0 += 16) {
        // Load A tile (128x16): 512 float4s, 2 per thread.
#pragma unroll
        for (int l = 0; l < 2; l++) {
            int f = tid + l * 256;      // 0..511
            int ar = f >> 2;            // 0..127 (m)
            int ac = (f & 3) * 4;       // 0,4,8,12 (k)
            float4 v = make_float4(0.f, 0.f, 0.f, 0.f);
            int grow = rowBase + ar;
            if (grow < M)
                v = *(const float4*)&A[(size_t)grow * K + k0 + ac];
            As[ac + 0][ar] = v.x;
            As[ac + 1][ar] = v.y;
            As[ac + 2][ar] = v.z;
            As[ac + 3][ar] = v.w;
        }
        // Load B tile (16x128): 512 float4s, 2 per thread.
#pragma unroll
        for (int l = 0; l < 2; l++) {
            int f = tid + l * 256;
            int br = f >> 5;            // 0..15 (k)
            int bc = (f & 31) * 4;      // 0..124 (n)
            float4 v = *(const float4*)&g_W[(size_t)(k0 + br) * DD + colBase + bc];
            *(float4*)&Bs[br][bc] = v;
        }
        __syncthreads();
#pragma unroll
        for (int kk = 0; kk < 16; kk++) {
            float ra[8], rb[8];
            float4 a0v = *(const float4*)&As[kk][ty * 8];
            float4 a1v = *(const float4*)&As[kk][ty * 8 + 4];
            float4 b0v = *(const float4*)&Bs[kk][tx * 8];
            float4 b1v = *(const float4*)&Bs[kk][tx * 8 + 4];
            ra[0] = a0v.x; ra[1] = a0v.y; ra[2] = a0v.z; ra[3] = a0v.w;
            ra[4] = a1v.x; ra[5] = a1v.y; ra[6] = a1v.z; ra[7] = a1v.w;
            rb[0] = b0v.x; rb[1] = b0v.y; rb[2] = b0v.z; rb[3] = b0v.w;
            rb[4] = b1v.x; rb[5] = b1v.y; rb[6] = b1v.z; rb[7] = b1v.w;
#pragma unroll
            for (int i = 0; i < 8; i++)
#pragma unroll
                for (int j = 0; j < 8; j++)
                    acc[i][j] = fmaf(ra[i], rb[j], acc[i][j]);
        }
        __syncthreads();
    }
    // Store
#pragma unroll
    for (int i = 0; i < 8; i++) {
        int grow = rowBase + ty * 8 + i;
        if (grow < M) {
#pragma unroll
            for (int j = 0; j < 8; j += 4) {
                float4 v = make_float4(acc[i][j], acc[i][j + 1], acc[i][j + 2], acc[i][j + 3]);
                *(float4*)&g_h[(size_t)grow * DD + colBase + tx * 8 + j] = v;
            }
        }
    }
}

// ---------------- gather + cross-relation mean + relu + LayerNorm ----------------
// One block (256 threads) per destination node; thread t owns feature dim t.
__global__ __launch_bounds__(256)
void agg_ln_kernel(const float* __restrict__ gamma,
                   const float* __restrict__ beta,
                   float* __restrict__ out, int n) {
    int v = blockIdx.x;
    if (v >= n) return;
    int tid = threadIdx.x;

    __shared__ int es[128];
    float acc = 0.f;

#pragma unroll
    for (int r = 0; r < 3; r++) {
        int dg = g_deg[r][v];          // uniform across block
        if (dg == 0) continue;
        int o = g_off[r][v];
        float accR = 0.f;
        for (int base = 0; base < dg; base += 128) {
            int cnt = min(128, dg - base);
            if (tid < cnt) es[tid] = g_csr[r][o + base + tid];
            __syncthreads();
#pragma unroll 4
            for (int i = 0; i < cnt; i++) {
                const float* hp = g_h + (size_t)es[i] * DD;
                accR += hp[tid];
            }
            __syncthreads();
        }
        acc += accR * (1.0f / (3.0f * (float)dg));
    }

    float x = fmaxf(acc, 0.f);

    // block reduce sum & sumsq over 256 lanes
    float s1 = x, s2 = x * x;
#pragma unroll
    for (int o = 16; o > 0; o >>= 1) {
        s1 += __shfl_xor_sync(0xFFFFFFFFu, s1, o);
        s2 += __shfl_xor_sync(0xFFFFFFFFu, s2, o);
    }
    __shared__ float w1[8], w2[8];
    int wid = tid >> 5, lane = tid & 31;
    if (lane == 0) { w1[wid] = s1; w2[wid] = s2; }
    __syncthreads();
    s1 = 0.f; s2 = 0.f;
#pragma unroll
    for (int i = 0; i < 8; i++) { s1 += w1[i]; s2 += w2[i]; }

    float mean = s1 * (1.0f / 256.0f);
    float var = s2 * (1.0f / 256.0f) - mean * mean;
    var = fmaxf(var, 0.f);
    float inv = rsqrtf(var + 1e-5f);
    out[(size_t)v * DD + tid] = (x - mean) * inv * gamma[tid] + beta[tid];
}

// ---------------- launch ----------------
extern "C" void kernel_launch(void* const* d_in, const int* in_sizes, int n_in,
                              void* d_out, int out_size) {
    const float* feat  = (const float*)d_in[0];
    const float* W0    = (const float*)d_in[1];
    const float* W1    = (const float*)d_in[2];
    const float* W2    = (const float*)d_in[3];
    // d_in[4..6] = a0,a1,a2 : softmax over size-1 tensors -> exactly 1/3 weights; unused.
    const float* gamma = (const float*)d_in[7];
    const float* beta  = (const float*)d_in[8];
    const int* src0 = (const int*)d_in[9];
    const int* dst0 = (const int*)d_in[10];
    const int* src1 = (const int*)d_in[11];
    const int* dst1 = (const int*)d_in[12];
    const int* src2 = (const int*)d_in[13];
    const int* dst2 = (const int*)d_in[14];

    int N = in_sizes[0] / DD;     // 50000
    int E = in_sizes[9];          // 400000

    // Lazily-created side stream + fork/join events (handles only; no device
    // memory). Work issued per call is identical every call.
    static cudaStream_t s_side = nullptr;
    static cudaEvent_t  ev_fork = nullptr, ev_join = nullptr;
    if (s_side == nullptr) {
        cudaStreamCreateWithFlags(&s_side, cudaStreamNonBlocking);
        cudaEventCreateWithFlags(&ev_fork, cudaEventDisableTiming);
        cudaEventCreateWithFlags(&ev_join, cudaEventDisableTiming);
    }

    // Fork: CSR-build chain runs on s_side, concurrent with the GEMM chain.
    cudaEventRecord(ev_fork, 0);
    cudaStreamWaitEvent(s_side, ev_fork, 0);

    // Branch B (side stream): CSR build
    zero_kernel<<<(3 * NN + 255) / 256, 256, 0, s_side>>>();
    deg_kernel<<<(3 * E + 255) / 256, 256, 0, s_side>>>(dst0, dst1, dst2, E);
    scan_kernel<<<3, 1024, 0, s_side>>>(N);
    fill_kernel<<<(3 * E + 255) / 256, 256, 0, s_side>>>(src0, dst0, src1, dst1,
                                                         src2, dst2, E);
    cudaEventRecord(ev_join, s_side);

    // Branch A (main stream): weight sum + GEMM
    wsum_kernel<<<(DD * DD + 255) / 256, 256>>>(W0, W1, W2);
    dim3 ggrid((N + 127) / 128, DD / 128);
    gemm_kernel<<<ggrid, 256>>>(feat, N);

    // Join: agg needs both g_h (branch A) and the CSR (branch B).
    cudaStreamWaitEvent(0, ev_join, 0);
    agg_ln_kernel<<<N, 256>>>(gamma, beta, (float*)d_out, N);
}

// round 14
// speedup vs baseline: 1.5838x; 1.0888x over previous
#include <cuda_runtime.h>
#include <cuda_bf16.h>
#include <mma.h>
#include <cstdint>

using namespace nvcuda;

// Problem constants (fixed shapes for this problem instance).
#define NN 50000
#define DD 256
#define EE 400000

// ---------------- device scratch (no allocations allowed) ----------------
__device__ float g_h[NN * DD];                  // h = feat @ Wsum (51.2 MB)
__device__ __nv_bfloat16 g_ahi[NN * DD];        // feat split hi (25.6 MB)
__device__ __nv_bfloat16 g_alo[NN * DD];        // feat split lo (25.6 MB)
__device__ __nv_bfloat16 g_whi[DD * DD];        // Wsum split hi
__device__ __nv_bfloat16 g_wlo[DD * DD];        // Wsum split lo
__device__ int g_deg[3][NN];
__device__ int g_off[3][NN];
__device__ int g_cur[3][NN];
__device__ int g_csr[3][EE];

// ---------------- tiny kernels ----------------
__global__ void zero_kernel() {
    int i = blockIdx.x * blockDim.x + threadIdx.x;
    if (i < 3 * NN) {
        (&g_deg[0][0])[i] = 0;
        (&g_cur[0][0])[i] = 0;
    }
}

// Wsum = (W0+W1+W2)/3, split into bf16 hi + lo (residual).
__global__ void wsplit_kernel(const float* __restrict__ W0,
                              const float* __restrict__ W1,
                              const float* __restrict__ W2) {
    int i = blockIdx.x * blockDim.x + threadIdx.x;
    if (i < DD * DD) {
        float w = (W0[i] + W1[i] + W2[i]) * (1.0f / 3.0f);
        __nv_bfloat16 hi = __float2bfloat16(w);
        float r = w - __bfloat162float(hi);
        g_whi[i] = hi;
        g_wlo[i] = __float2bfloat16(r);
    }
}

// feat -> bf16 hi/lo split, vectorized float4.
__global__ void fsplit_kernel(const float* __restrict__ feat) {
    int i = blockIdx.x * blockDim.x + threadIdx.x;   // float4 index
    const int total4 = NN * DD / 4;
    if (i >= total4) return;
    float4 v = ((const float4*)feat)[i];
    __nv_bfloat16 h0 = __float2bfloat16(v.x);
    __nv_bfloat16 h1 = __float2bfloat16(v.y);
    __nv_bfloat16 h2 = __float2bfloat16(v.z);
    __nv_bfloat16 h3 = __float2bfloat16(v.w);
    __nv_bfloat16 l0 = __float2bfloat16(v.x - __bfloat162float(h0));
    __nv_bfloat16 l1 = __float2bfloat16(v.y - __bfloat162float(h1));
    __nv_bfloat16 l2 = __float2bfloat16(v.z - __bfloat162float(h2));
    __nv_bfloat16 l3 = __float2bfloat16(v.w - __bfloat162float(h3));
    __nv_bfloat162 hi01, hi23, lo01, lo23;
    hi01.x = h0; hi01.y = h1; hi23.x = h2; hi23.y = h3;
    lo01.x = l0; lo01.y = l1; lo23.x = l2; lo23.y = l3;
    ((__nv_bfloat162*)g_ahi)[i * 2 + 0] = hi01;
    ((__nv_bfloat162*)g_ahi)[i * 2 + 1] = hi23;
    ((__nv_bfloat162*)g_alo)[i * 2 + 0] = lo01;
    ((__nv_bfloat162*)g_alo)[i * 2 + 1] = lo23;
}

__global__ void deg_kernel(const int* __restrict__ d0,
                           const int* __restrict__ d1,
                           const int* __restrict__ d2, int E) {
    int i = blockIdx.x * blockDim.x + threadIdx.x;
    if (i >= 3 * E) return;
    int r = i / E;
    int e = i - r * E;
    const int* dp = (r == 0) ? d0 : (r == 1) ? d1 : d2;
    atomicAdd(&g_deg[r][dp[e]], 1);
}

// One block per relation: coalesced tiled scan (warp shuffles + carry).
__global__ __launch_bounds__(1024)
void scan_kernel(int n) {
    int r = blockIdx.x;
    int tid = threadIdx.x;
    int lane = tid & 31, wid = tid >> 5;
    const int* deg = g_deg[r];
    int* off = g_off[r];

    __shared__ int warpsum[32];
    __shared__ int s_carry;
    if (tid == 0) s_carry = 0;
    __syncthreads();

    for (int base = 0; base < n; base += 1024) {
        int idx = base + tid;
        int v = (idx < n) ? deg[idx] : 0;
        int x = v;
#pragma unroll
        for (int o = 1; o < 32; o <<= 1) {
            int t = __shfl_up_sync(0xFFFFFFFFu, x, o);
            if (lane >= o) x += t;
        }
        if (lane == 31) warpsum[wid] = x;
        __syncthreads();
        if (wid == 0) {
            int w = warpsum[lane];
#pragma unroll
            for (int o = 1; o < 32; o <<= 1) {
                int t = __shfl_up_sync(0xFFFFFFFFu, w, o);
                if (lane >= o) w += t;
            }
            warpsum[lane] = w;
        }
        __syncthreads();
        int carry = s_carry;
        int excl = carry + (wid ? warpsum[wid - 1] : 0) + x - v;
        if (idx < n) off[idx] = excl;
        __syncthreads();
        if (tid == 0) s_carry = carry + warpsum[31];
        __syncthreads();
    }
}

__global__ void fill_kernel(const int* __restrict__ s0, const int* __restrict__ d0,
                            const int* __restrict__ s1, const int* __restrict__ d1,
                            const int* __restrict__ s2, const int* __restrict__ d2,
                            int E) {
    int i = blockIdx.x * blockDim.x + threadIdx.x;
    if (i >= 3 * E) return;
    int r = i / E;
    int e = i - r * E;
    const int* sp = (r == 0) ? s0 : (r == 1) ? s1 : s2;
    const int* dp = (r == 0) ? d0 : (r == 1) ? d1 : d2;
    int dst = dp[e];
    int pos = g_off[r][dst] + atomicAdd(&g_cur[r][dst], 1);
    g_csr[r][pos] = sp[e];
}

// ---------------- split-bf16 tensor-core GEMM ----------------
// g_h[M,256] = sum over terms { Ahi@Whi + Ahi@Wlo + Alo@Whi }, fp32 accum.
// 128x128 block tile, BK=64, 8 warps, warp tile 32x64 (2x4 wmma 16x16x16).
#define LDA 72    // 64 + 8 pad (bf16 elements)
#define LDB 136   // 128 + 8 pad

__global__ __launch_bounds__(256)
void gemm_bf16_kernel(int M) {
    __shared__ __nv_bfloat16 As[128 * LDA];
    __shared__ __nv_bfloat16 Bs[64 * LDB];

    int tid = threadIdx.x;
    int w = tid >> 5;
    int wm = w & 3;            // 0..3 -> rows wm*32
    int wn = w >> 2;           // 0..1 -> cols wn*64
    int rowBase = blockIdx.x * 128;
    int colBase = blockIdx.y * 128;

    wmma::fragment<wmma::accumulator, 16, 16, 16, float> c[2][4];
#pragma unroll
    for (int i = 0; i < 2; i++)
#pragma unroll
        for (int j = 0; j < 4; j++) wmma::fill_fragment(c[i][j], 0.0f);

    const __nv_bfloat16* Aterm[3] = { g_ahi, g_ahi, g_alo };
    const __nv_bfloat16* Bterm[3] = { g_whi, g_wlo, g_whi };

#pragma unroll
    for (int t = 0; t < 3; t++) {
        const __nv_bfloat16* Ap = Aterm[t];
        const __nv_bfloat16* Bp = Bterm[t];
        for (int k0 = 0; k0 < DD; k0 += 64) {
            // Load A tile 128x64: 1024 16B-vectors (8 bf16), 4 per thread.
#pragma unroll
            for (int l = 0; l < 4; l++) {
                int f = tid + l * 256;         // 0..1023
                int ar = f >> 3;               // 0..127
                int ac = (f & 7) * 8;          // 0..56
                uint4 v = make_uint4(0u, 0u, 0u, 0u);
                int grow = rowBase + ar;
                if (grow < M)
                    v = *(const uint4*)&Ap[(size_t)grow * DD + k0 + ac];
                *(uint4*)&As[ar * LDA + ac] = v;
            }
            // Load B tile 64x128: 1024 vectors, 4 per thread.
#pragma unroll
            for (int l = 0; l < 4; l++) {
                int f = tid + l * 256;
                int br = f >> 4;               // 0..63
                int bc = (f & 15) * 8;         // 0..120
                uint4 v = *(const uint4*)&Bp[(size_t)(k0 + br) * DD + colBase + bc];
                *(uint4*)&Bs[br * LDB + bc] = v;
            }
            __syncthreads();
#pragma unroll
            for (int kk = 0; kk < 4; kk++) {
                wmma::fragment<wmma::matrix_a, 16, 16, 16, __nv_bfloat16, wmma::row_major> a[2];
                wmma::fragment<wmma::matrix_b, 16, 16, 16, __nv_bfloat16, wmma::row_major> b[4];
#pragma unroll
                for (int i = 0; i < 2; i++)
                    wmma::load_matrix_sync(a[i], &As[(wm * 32 + i * 16) * LDA + kk * 16], LDA);
#pragma unroll
                for (int j = 0; j < 4; j++)
                    wmma::load_matrix_sync(b[j], &Bs[(kk * 16) * LDB + wn * 64 + j * 16], LDB);
#pragma unroll
                for (int i = 0; i < 2; i++)
#pragma unroll
                    for (int j = 0; j < 4; j++)
                        wmma::mma_sync(c[i][j], a[i], b[j], c[i][j]);
            }
            __syncthreads();
        }
    }

    // Store. M is a multiple of 16, so each 16-row tile is fully in or out.
#pragma unroll
    for (int i = 0; i < 2; i++) {
        int rowTile = rowBase + wm * 32 + i * 16;
        if (rowTile < M) {
#pragma unroll
            for (int j = 0; j < 4; j++) {
                wmma::store_matrix_sync(
                    &g_h[(size_t)rowTile * DD + colBase + wn * 64 + j * 16],
                    c[i][j], DD, wmma::mem_row_major);
            }
        }
    }
}

// ---------------- gather + cross-relation mean + relu + LayerNorm ----------------
__global__ __launch_bounds__(256)
void agg_ln_kernel(const float* __restrict__ gamma,
                   const float* __restrict__ beta,
                   float* __restrict__ out, int n) {
    int v = blockIdx.x;
    if (v >= n) return;
    int tid = threadIdx.x;

    __shared__ int es[128];
    float acc = 0.f;

#pragma unroll
    for (int r = 0; r < 3; r++) {
        int dg = g_deg[r][v];
        if (dg == 0) continue;
        int o = g_off[r][v];
        float accR = 0.f;
        for (int base = 0; base < dg; base += 128) {
            int cnt = min(128, dg - base);
            if (tid < cnt) es[tid] = g_csr[r][o + base + tid];
            __syncthreads();
#pragma unroll 4
            for (int i = 0; i < cnt; i++) {
                const float* hp = g_h + (size_t)es[i] * DD;
                accR += hp[tid];
            }
            __syncthreads();
        }
        acc += accR * (1.0f / (3.0f * (float)dg));
    }

    float x = fmaxf(acc, 0.f);

    float s1 = x, s2 = x * x;
#pragma unroll
    for (int o = 16; o > 0; o >>= 1) {
        s1 += __shfl_xor_sync(0xFFFFFFFFu, s1, o);
        s2 += __shfl_xor_sync(0xFFFFFFFFu, s2, o);
    }
    __shared__ float w1[8], w2[8];
    int wid = tid >> 5, lane = tid & 31;
    if (lane == 0) { w1[wid] = s1; w2[wid] = s2; }
    __syncthreads();
    s1 = 0.f; s2 = 0.f;
#pragma unroll
    for (int i = 0; i < 8; i++) { s1 += w1[i]; s2 += w2[i]; }

    float mean = s1 * (1.0f / 256.0f);
    float var = s2 * (1.0f / 256.0f) - mean * mean;
    var = fmaxf(var, 0.f);
    float inv = rsqrtf(var + 1e-5f);
    out[(size_t)v * DD + tid] = (x - mean) * inv * gamma[tid] + beta[tid];
}

// ---------------- launch ----------------
extern "C" void kernel_launch(void* const* d_in, const int* in_sizes, int n_in,
                              void* d_out, int out_size) {
    const float* feat  = (const float*)d_in[0];
    const float* W0    = (const float*)d_in[1];
    const float* W1    = (const float*)d_in[2];
    const float* W2    = (const float*)d_in[3];
    // d_in[4..6] = a0,a1,a2 : softmax over size-1 tensors -> exactly 1/3 weights; unused.
    const float* gamma = (const float*)d_in[7];
    const float* beta  = (const float*)d_in[8];
    const int* src0 = (const int*)d_in[9];
    const int* dst0 = (const int*)d_in[10];
    const int* src1 = (const int*)d_in[11];
    const int* dst1 = (const int*)d_in[12];
    const int* src2 = (const int*)d_in[13];
    const int* dst2 = (const int*)d_in[14];

    int N = in_sizes[0] / DD;     // 50000
    int E = in_sizes[9];          // 400000

    static cudaStream_t s_side = nullptr;
    static cudaEvent_t  ev_fork = nullptr, ev_join = nullptr;
    if (s_side == nullptr) {
        cudaStreamCreateWithFlags(&s_side, cudaStreamNonBlocking);
        cudaEventCreateWithFlags(&ev_fork, cudaEventDisableTiming);
        cudaEventCreateWithFlags(&ev_join, cudaEventDisableTiming);
    }

    // Fork: CSR-build chain runs on s_side, concurrent with the GEMM chain.
    cudaEventRecord(ev_fork, 0);
    cudaStreamWaitEvent(s_side, ev_fork, 0);

    // Branch B (side stream): CSR build
    zero_kernel<<<(3 * NN + 255) / 256, 256, 0, s_side>>>();
    deg_kernel<<<(3 * E + 255) / 256, 256, 0, s_side>>>(dst0, dst1, dst2, E);
    scan_kernel<<<3, 1024, 0, s_side>>>(N);
    fill_kernel<<<(3 * E + 255) / 256, 256, 0, s_side>>>(src0, dst0, src1, dst1,
                                                         src2, dst2, E);
    cudaEventRecord(ev_join, s_side);

    // Branch A (main stream): weight split + feat split + tensor-core GEMM
    wsplit_kernel<<<(DD * DD + 255) / 256, 256>>>(W0, W1, W2);
    fsplit_kernel<<<(NN * DD / 4 + 255) / 256, 256>>>(feat);
    dim3 ggrid((N + 127) / 128, DD / 128);
    gemm_bf16_kernel<<<ggrid, 256>>>(N);

    // Join: agg needs both g_h (branch A) and the CSR (branch B).
    cudaStreamWaitEvent(0, ev_join, 0);
    agg_ln_kernel<<<N, 256>>>(gamma, beta, (float*)d_out, N);
}

// round 15
// speedup vs baseline: 2.1147x; 1.3352x over previous
#include <cuda_runtime.h>
#include <cuda_bf16.h>
#include <mma.h>
#include <cstdint>

using namespace nvcuda;

// Problem constants (fixed shapes for this problem instance).
#define NN 50000
#define DD 256
#define EE 400000

// ---------------- device scratch (no allocations allowed) ----------------
__device__ float g_h[NN * DD];                  // h = feat @ Wsum (51.2 MB)
__device__ __nv_bfloat16 g_ahi[NN * DD];        // feat split hi (25.6 MB)
__device__ __nv_bfloat16 g_alo[NN * DD];        // feat split lo (25.6 MB)
__device__ __nv_bfloat16 g_whi[DD * DD];        // Wsum split hi
__device__ __nv_bfloat16 g_wlo[DD * DD];        // Wsum split lo
__device__ int g_deg[3][NN];
__device__ int g_off[3][NN];
__device__ int g_cur[3][NN];
__device__ int g_csr[3][EE];

// ---------------- cp.async helpers ----------------
__device__ __forceinline__ void cp_async16(void* smem_dst, const void* gsrc) {
    uint32_t s = (uint32_t)__cvta_generic_to_shared(smem_dst);
    asm volatile("cp.async.cg.shared.global [%0], [%1], 16;" :: "r"(s), "l"(gsrc));
}
__device__ __forceinline__ void cp_commit() {
    asm volatile("cp.async.commit_group;");
}
template <int N>
__device__ __forceinline__ void cp_wait() {
    asm volatile("cp.async.wait_group %0;" :: "n"(N));
}

// ---------------- tiny kernels ----------------
__global__ void zero_kernel() {
    int i = blockIdx.x * blockDim.x + threadIdx.x;
    if (i < 3 * NN) {
        (&g_deg[0][0])[i] = 0;
        (&g_cur[0][0])[i] = 0;
    }
}

// Wsum = (W0+W1+W2)/3, split into bf16 hi + lo (residual).
__global__ void wsplit_kernel(const float* __restrict__ W0,
                              const float* __restrict__ W1,
                              const float* __restrict__ W2) {
    int i = blockIdx.x * blockDim.x + threadIdx.x;
    if (i < DD * DD) {
        float w = (W0[i] + W1[i] + W2[i]) * (1.0f / 3.0f);
        __nv_bfloat16 hi = __float2bfloat16(w);
        float r = w - __bfloat162float(hi);
        g_whi[i] = hi;
        g_wlo[i] = __float2bfloat16(r);
    }
}

// feat -> bf16 hi/lo split, vectorized float4.
__global__ void fsplit_kernel(const float* __restrict__ feat) {
    int i = blockIdx.x * blockDim.x + threadIdx.x;   // float4 index
    const int total4 = NN * DD / 4;
    if (i >= total4) return;
    float4 v = ((const float4*)feat)[i];
    __nv_bfloat16 h0 = __float2bfloat16(v.x);
    __nv_bfloat16 h1 = __float2bfloat16(v.y);
    __nv_bfloat16 h2 = __float2bfloat16(v.z);
    __nv_bfloat16 h3 = __float2bfloat16(v.w);
    __nv_bfloat16 l0 = __float2bfloat16(v.x - __bfloat162float(h0));
    __nv_bfloat16 l1 = __float2bfloat16(v.y - __bfloat162float(h1));
    __nv_bfloat16 l2 = __float2bfloat16(v.z - __bfloat162float(h2));
    __nv_bfloat16 l3 = __float2bfloat16(v.w - __bfloat162float(h3));
    __nv_bfloat162 hi01, hi23, lo01, lo23;
    hi01.x = h0; hi01.y = h1; hi23.x = h2; hi23.y = h3;
    lo01.x = l0; lo01.y = l1; lo23.x = l2; lo23.y = l3;
    ((__nv_bfloat162*)g_ahi)[i * 2 + 0] = hi01;
    ((__nv_bfloat162*)g_ahi)[i * 2 + 1] = hi23;
    ((__nv_bfloat162*)g_alo)[i * 2 + 0] = lo01;
    ((__nv_bfloat162*)g_alo)[i * 2 + 1] = lo23;
}

__global__ void deg_kernel(const int* __restrict__ d0,
                           const int* __restrict__ d1,
                           const int* __restrict__ d2, int E) {
    int i = blockIdx.x * blockDim.x + threadIdx.x;
    if (i >= 3 * E) return;
    int r = i / E;
    int e = i - r * E;
    const int* dp = (r == 0) ? d0 : (r == 1) ? d1 : d2;
    atomicAdd(&g_deg[r][dp[e]], 1);
}

// One block per relation: coalesced tiled scan (warp shuffles + carry).
__global__ __launch_bounds__(1024)
void scan_kernel(int n) {
    int r = blockIdx.x;
    int tid = threadIdx.x;
    int lane = tid & 31, wid = tid >> 5;
    const int* deg = g_deg[r];
    int* off = g_off[r];

    __shared__ int warpsum[32];
    __shared__ int s_carry;
    if (tid == 0) s_carry = 0;
    __syncthreads();

    for (int base = 0; base < n; base += 1024) {
        int idx = base + tid;
        int v = (idx < n) ? deg[idx] : 0;
        int x = v;
#pragma unroll
        for (int o = 1; o < 32; o <<= 1) {
            int t = __shfl_up_sync(0xFFFFFFFFu, x, o);
            if (lane >= o) x += t;
        }
        if (lane == 31) warpsum[wid] = x;
        __syncthreads();
        if (wid == 0) {
            int w = warpsum[lane];
#pragma unroll
            for (int o = 1; o < 32; o <<= 1) {
                int t = __shfl_up_sync(0xFFFFFFFFu, w, o);
                if (lane >= o) w += t;
            }
            warpsum[lane] = w;
        }
        __syncthreads();
        int carry = s_carry;
        int excl = carry + (wid ? warpsum[wid - 1] : 0) + x - v;
        if (idx < n) off[idx] = excl;
        __syncthreads();
        if (tid == 0) s_carry = carry + warpsum[31];
        __syncthreads();
    }
}

__global__ void fill_kernel(const int* __restrict__ s0, const int* __restrict__ d0,
                            const int* __restrict__ s1, const int* __restrict__ d1,
                            const int* __restrict__ s2, const int* __restrict__ d2,
                            int E) {
    int i = blockIdx.x * blockDim.x + threadIdx.x;
    if (i >= 3 * E) return;
    int r = i / E;
    int e = i - r * E;
    const int* sp = (r == 0) ? s0 : (r == 1) ? s1 : s2;
    const int* dp = (r == 0) ? d0 : (r == 1) ? d1 : d2;
    int dst = dp[e];
    int pos = g_off[r][dst] + atomicAdd(&g_cur[r][dst], 1);
    g_csr[r][pos] = sp[e];
}

// ---------------- split-bf16 tensor-core GEMM, cp.async double-buffered ------
// g_h[M,256] = Ahi@Whi + Ahi@Wlo + Alo@Whi (fp32 accum), expressed as a single
// virtual K=768 loop: kt=0..23, term=kt/8, k0=(kt%8)*32, BK=32, 2 smem stages.
#define BK   32
#define LDA  40    // 32 + 8 pad (bf16 elems)
#define LDB  136   // 128 + 8 pad
#define KT_TOTAL 24

__global__ __launch_bounds__(256, 2)
void gemm_bf16_kernel(int M) {
    __shared__ __nv_bfloat16 As[2][128 * LDA];   // 2 x 10.0 KB
    __shared__ __nv_bfloat16 Bs[2][BK * LDB];    // 2 x 8.5 KB

    int tid = threadIdx.x;
    int w = tid >> 5;
    int wm = w & 3;            // rows wm*32
    int wn = w >> 2;           // cols wn*64
    int rowBase = blockIdx.x * 128;
    int colBase = blockIdx.y * 128;

    wmma::fragment<wmma::accumulator, 16, 16, 16, float> c[2][4];
#pragma unroll
    for (int i = 0; i < 2; i++)
#pragma unroll
        for (int j = 0; j < 4; j++) wmma::fill_fragment(c[i][j], 0.0f);

    // Per-thread load coordinates (fixed across iterations).
    // A tile 128x32 bf16 = 512 16B-vectors -> 2 per thread.
    int a_r0 = tid >> 1;                 // one of 2 vectors: rows tid/2 (+64?) no:
    // 512 vectors: v = tid + l*256, row = v>>2, col8 = (v&3)*8
    // B tile 32x128 = 512 vectors likewise.

    auto issue = [&](int s, int kt) {
        int t = kt >> 3;
        int k0 = (kt & 7) * BK;
        const __nv_bfloat16* Ap = (t < 2) ? g_ahi : g_alo;
        const __nv_bfloat16* Bp = (t == 1) ? g_wlo : g_whi;
#pragma unroll
        for (int l = 0; l < 2; l++) {
            int f = tid + l * 256;       // 0..511
            int ar = f >> 2;             // 0..127
            int ac = (f & 3) * 8;        // 0,8,16,24
            __nv_bfloat16* dst = &As[s][ar * LDA + ac];
            int grow = rowBase + ar;
            if (grow < M)
                cp_async16(dst, &Ap[(size_t)grow * DD + k0 + ac]);
            else
                *(uint4*)dst = make_uint4(0u, 0u, 0u, 0u);
        }
#pragma unroll
        for (int l = 0; l < 2; l++) {
            int f = tid + l * 256;       // 0..511
            int br = f >> 4;             // 0..31
            int bc = (f & 15) * 8;       // 0..120
            cp_async16(&Bs[s][br * LDB + bc],
                       &Bp[(size_t)(k0 + br) * DD + colBase + bc]);
        }
        cp_commit();
    };

    issue(0, 0);
    for (int kt = 0; kt < KT_TOTAL; kt++) {
        int s = kt & 1;
        if (kt + 1 < KT_TOTAL) {
            issue(s ^ 1, kt + 1);
            cp_wait<1>();                // current stage's group done; prefetch in flight
        } else {
            cp_wait<0>();
        }
        __syncthreads();

#pragma unroll
        for (int kk = 0; kk < 2; kk++) {
            wmma::fragment<wmma::matrix_a, 16, 16, 16, __nv_bfloat16, wmma::row_major> a[2];
            wmma::fragment<wmma::matrix_b, 16, 16, 16, __nv_bfloat16, wmma::row_major> b[4];
#pragma unroll
            for (int i = 0; i < 2; i++)
                wmma::load_matrix_sync(a[i], &As[s][(wm * 32 + i * 16) * LDA + kk * 16], LDA);
#pragma unroll
            for (int j = 0; j < 4; j++)
                wmma::load_matrix_sync(b[j], &Bs[s][(kk * 16) * LDB + wn * 64 + j * 16], LDB);
#pragma unroll
            for (int i = 0; i < 2; i++)
#pragma unroll
                for (int j = 0; j < 4; j++)
                    wmma::mma_sync(c[i][j], a[i], b[j], c[i][j]);
        }
        __syncthreads();                 // stage s reusable for kt+2's loads
    }

    // Store. M is a multiple of 16, so each 16-row tile is fully in or out.
#pragma unroll
    for (int i = 0; i < 2; i++) {
        int rowTile = rowBase + wm * 32 + i * 16;
        if (rowTile < M) {
#pragma unroll
            for (int j = 0; j < 4; j++) {
                wmma::store_matrix_sync(
                    &g_h[(size_t)rowTile * DD + colBase + wn * 64 + j * 16],
                    c[i][j], DD, wmma::mem_row_major);
            }
        }
    }
}

// ---------------- gather + cross-relation mean + relu + LayerNorm ------------
// One block (256 threads) per destination node; thread t owns feature dim t.
// All 3 relations' edges staged into ONE combined (index, weight) list so the
// gather loop exposes the full ~deg_total MLP between barriers.
__global__ __launch_bounds__(256)
void agg_ln_kernel(const float* __restrict__ gamma,
                   const float* __restrict__ beta,
                   float* __restrict__ out, int n) {
    int v = blockIdx.x;
    if (v >= n) return;
    int tid = threadIdx.x;

    __shared__ int   es[256];
    __shared__ float ws[256];

    int dg0 = g_deg[0][v], dg1 = g_deg[1][v], dg2 = g_deg[2][v];
    int o0 = g_off[0][v], o1 = g_off[1][v], o2 = g_off[2][v];
    int b1 = dg0, b2 = dg0 + dg1;
    int T = dg0 + dg1 + dg2;
    float w0 = dg0 ? 1.0f / (3.0f * (float)dg0) : 0.f;
    float w1 = dg1 ? 1.0f / (3.0f * (float)dg1) : 0.f;
    float w2 = dg2 ? 1.0f / (3.0f * (float)dg2) : 0.f;

    float acc = 0.f;
    for (int base = 0; base < T; base += 256) {
        int j = base + tid;
        int cnt = min(256, T - base);
        if (j < T) {
            int idx; float wt;
            if (j < b1)      { idx = g_csr[0][o0 + j];      wt = w0; }
            else if (j < b2) { idx = g_csr[1][o1 + j - b1]; wt = w1; }
            else             { idx = g_csr[2][o2 + j - b2]; wt = w2; }
            es[tid] = idx;
            ws[tid] = wt;
        }
        __syncthreads();
#pragma unroll 8
        for (int i = 0; i < cnt; i++)
            acc += g_h[(size_t)es[i] * DD + tid] * ws[i];
        __syncthreads();
    }

    float x = fmaxf(acc, 0.f);

    float s1 = x, s2 = x * x;
#pragma unroll
    for (int o = 16; o > 0; o >>= 1) {
        s1 += __shfl_xor_sync(0xFFFFFFFFu, s1, o);
        s2 += __shfl_xor_sync(0xFFFFFFFFu, s2, o);
    }
    __shared__ float r1[8], r2[8];
    int wid = tid >> 5, lane = tid & 31;
    if (lane == 0) { r1[wid] = s1; r2[wid] = s2; }
    __syncthreads();
    s1 = 0.f; s2 = 0.f;
#pragma unroll
    for (int i = 0; i < 8; i++) { s1 += r1[i]; s2 += r2[i]; }

    float mean = s1 * (1.0f / 256.0f);
    float var = s2 * (1.0f / 256.0f) - mean * mean;
    var = fmaxf(var, 0.f);
    float inv = rsqrtf(var + 1e-5f);
    out[(size_t)v * DD + tid] = (x - mean) * inv * gamma[tid] + beta[tid];
}

// ---------------- launch ----------------
extern "C" void kernel_launch(void* const* d_in, const int* in_sizes, int n_in,
                              void* d_out, int out_size) {
    const float* feat  = (const float*)d_in[0];
    const float* W0    = (const float*)d_in[1];
    const float* W1    = (const float*)d_in[2];
    const float* W2    = (const float*)d_in[3];
    // d_in[4..6] = a0,a1,a2 : softmax over size-1 tensors -> exactly 1/3 weights; unused.
    const float* gamma = (const float*)d_in[7];
    const float* beta  = (const float*)d_in[8];
    const int* src0 = (const int*)d_in[9];
    const int* dst0 = (const int*)d_in[10];
    const int* src1 = (const int*)d_in[11];
    const int* dst1 = (const int*)d_in[12];
    const int* src2 = (const int*)d_in[13];
    const int* dst2 = (const int*)d_in[14];

    int N = in_sizes[0] / DD;     // 50000
    int E = in_sizes[9];          // 400000

    static cudaStream_t s_side = nullptr;
    static cudaEvent_t  ev_fork = nullptr, ev_join = nullptr;
    if (s_side == nullptr) {
        cudaStreamCreateWithFlags(&s_side, cudaStreamNonBlocking);
        cudaEventCreateWithFlags(&ev_fork, cudaEventDisableTiming);
        cudaEventCreateWithFlags(&ev_join, cudaEventDisableTiming);
    }

    // Fork: CSR-build chain runs on s_side, concurrent with the GEMM chain.
    cudaEventRecord(ev_fork, 0);
    cudaStreamWaitEvent(s_side, ev_fork, 0);

    // Branch B (side stream): CSR build
    zero_kernel<<<(3 * NN + 255) / 256, 256, 0, s_side>>>();
    deg_kernel<<<(3 * E + 255) / 256, 256, 0, s_side>>>(dst0, dst1, dst2, E);
    scan_kernel<<<3, 1024, 0, s_side>>>(N);
    fill_kernel<<<(3 * E + 255) / 256, 256, 0, s_side>>>(src0, dst0, src1, dst1,
                                                         src2, dst2, E);
    cudaEventRecord(ev_join, s_side);

    // Branch A (main stream): weight split + feat split + tensor-core GEMM
    wsplit_kernel<<<(DD * DD + 255) / 256, 256>>>(W0, W1, W2);
    fsplit_kernel<<<(NN * DD / 4 + 255) / 256, 256>>>(feat);
    dim3 ggrid((N + 127) / 128, DD / 128);
    gemm_bf16_kernel<<<ggrid, 256>>>(N);

    // Join: agg needs both g_h (branch A) and the CSR (branch B).
    cudaStreamWaitEvent(0, ev_join, 0);
    agg_ln_kernel<<<N, 256>>>(gamma, beta, (float*)d_out, N);
}